// round 4
// baseline (speedup 1.0000x reference)
#include <cuda_runtime.h>
#include <math.h>

#define HH   112
#define WW   112
#define HWSZ 12544          // 112*112
#define BB   2
#define NPIX 25088          // B*H*W
#define CC   64
#define N2   49
#define RR   3

// ---------------- scratch (pixel-major layouts) ----------------
__device__ float g_sem [NPIX * CC];   // semantic, [pix][c]
__device__ float g_spa [NPIX * CC];   // spatial,  [pix][c]
__device__ float g_px  [NPIX * CC];   // range_proj output
__device__ float g_pxsq[NPIX];        // sum_c px^2 per pixel
__device__ float g_mid [NPIX * CC];   // neighborhood-reduced feats
__device__ float g_o2  [NPIX * CC];   // output_proj result (pixel-major)

// ---------------- K0: [B,C,HW] -> [pix,C] transpose ----------------
__global__ void k_t_c2p(const float* __restrict__ src, float* __restrict__ dst) {
    __shared__ float s[64][33];
    int b  = blockIdx.y;
    int p0 = blockIdx.x * 32;
    int tx = threadIdx.x, ty = threadIdx.y;        // 32 x 8
    #pragma unroll
    for (int c = ty; c < 64; c += 8)
        s[c][tx] = src[(b * 64 + c) * HWSZ + p0 + tx];
    __syncthreads();
    #pragma unroll
    for (int i = ty; i < 32; i += 8) {
        int base = (b * HWSZ + p0 + i) * 64;
        dst[base + tx]      = s[tx][i];
        dst[base + 32 + tx] = s[tx + 32][i];
    }
}

// ---------------- K4: [pix,C] -> [B,C,HW] transpose ----------------
__global__ void k_t_p2c(const float* __restrict__ src, float* __restrict__ dst) {
    __shared__ float s[64][33];
    int b  = blockIdx.y;
    int p0 = blockIdx.x * 32;
    int tx = threadIdx.x, ty = threadIdx.y;
    #pragma unroll
    for (int i = ty; i < 32; i += 8) {
        int base = (b * HWSZ + p0 + i) * 64;
        s[tx][i]      = src[base + tx];
        s[tx + 32][i] = src[base + 32 + tx];
    }
    __syncthreads();
    #pragma unroll
    for (int c = ty; c < 64; c += 8)
        dst[(b * 64 + c) * HWSZ + p0 + tx] = s[c][tx];
}

// ---------------- K1/K3: conv1x1 -> LN -> (SiLU) -> conv1x1 ----------------
// pixel-major in/out. One warp processes 4 pixels; 8 warps/block => 32 pix/iter.
template<bool SILU, bool WSQ>
__global__ void __launch_bounds__(256)
k_proj(const float* __restrict__ in, float* __restrict__ out, float* __restrict__ sq,
       const float* __restrict__ w1, const float* __restrict__ b1,
       const float* __restrict__ gg, const float* __restrict__ bb,
       const float* __restrict__ w2, const float* __restrict__ b2)
{
    __shared__ float w1t[64 * 64];           // w1t[k*64+o] = w1[o*64+k]
    __shared__ float w2t[64 * 64];
    __shared__ float xb[8][4][64];

    int tid = threadIdx.x;
    for (int t = tid; t < 4096; t += 256) {
        int o = t >> 6, k = t & 63;
        w1t[k * 64 + o] = w1[t];
        w2t[k * 64 + o] = w2[t];
    }
    __syncthreads();

    int warp = tid >> 5, lane = tid & 31;
    int o0 = 2 * lane, o1 = o0 + 1;
    float b1a = b1[o0], b1b = b1[o1];
    float b2a = b2[o0], b2b = b2[o1];
    float ga  = gg[o0], gb  = gg[o1];
    float bea = bb[o0], beb = bb[o1];

    for (int base = blockIdx.x * 32; base < NPIX; base += gridDim.x * 32) {
        int pix0 = base + warp * 4;

        #pragma unroll
        for (int pp = 0; pp < 4; pp++) {
            float2 v = *(const float2*)&in[(pix0 + pp) * 64 + o0];
            xb[warp][pp][o0] = v.x;
            xb[warp][pp][o1] = v.y;
        }
        __syncwarp();

        float2 acc[4];
        #pragma unroll
        for (int pp = 0; pp < 4; pp++) acc[pp] = make_float2(b1a, b1b);
        #pragma unroll 8
        for (int k = 0; k < 64; k++) {
            float2 wv = *(const float2*)&w1t[k * 64 + o0];
            float x0 = xb[warp][0][k], x1 = xb[warp][1][k];
            float x2 = xb[warp][2][k], x3 = xb[warp][3][k];
            acc[0].x += wv.x * x0; acc[0].y += wv.y * x0;
            acc[1].x += wv.x * x1; acc[1].y += wv.y * x1;
            acc[2].x += wv.x * x2; acc[2].y += wv.y * x2;
            acc[3].x += wv.x * x3; acc[3].y += wv.y * x3;
        }
        __syncwarp();

        // LayerNorm (+SiLU) per pixel over 64 channels; write back into xb
        #pragma unroll
        for (int pp = 0; pp < 4; pp++) {
            float s = acc[pp].x + acc[pp].y;
            float q = acc[pp].x * acc[pp].x + acc[pp].y * acc[pp].y;
            #pragma unroll
            for (int off = 16; off; off >>= 1) {
                s += __shfl_xor_sync(0xffffffffu, s, off);
                q += __shfl_xor_sync(0xffffffffu, q, off);
            }
            float mean = s * (1.f / 64.f);
            float var  = q * (1.f / 64.f) - mean * mean;
            float rstd = rsqrtf(var + 1e-6f);
            float v0 = ga * (acc[pp].x - mean) * rstd + bea;
            float v1 = gb * (acc[pp].y - mean) * rstd + beb;
            if (SILU) {
                v0 = v0 / (1.f + __expf(-v0));
                v1 = v1 / (1.f + __expf(-v1));
            }
            xb[warp][pp][o0] = v0;
            xb[warp][pp][o1] = v1;
        }
        __syncwarp();

        #pragma unroll
        for (int pp = 0; pp < 4; pp++) acc[pp] = make_float2(b2a, b2b);
        #pragma unroll 8
        for (int k = 0; k < 64; k++) {
            float2 wv = *(const float2*)&w2t[k * 64 + o0];
            float x0 = xb[warp][0][k], x1 = xb[warp][1][k];
            float x2 = xb[warp][2][k], x3 = xb[warp][3][k];
            acc[0].x += wv.x * x0; acc[0].y += wv.y * x0;
            acc[1].x += wv.x * x1; acc[1].y += wv.y * x1;
            acc[2].x += wv.x * x2; acc[2].y += wv.y * x2;
            acc[3].x += wv.x * x3; acc[3].y += wv.y * x3;
        }

        #pragma unroll
        for (int pp = 0; pp < 4; pp++) {
            *(float2*)&out[(pix0 + pp) * 64 + o0] = acc[pp];
            if (WSQ) {
                float t = acc[pp].x * acc[pp].x + acc[pp].y * acc[pp].y;
                #pragma unroll
                for (int off = 16; off; off >>= 1)
                    t += __shfl_xor_sync(0xffffffffu, t, off);
                if (lane == 0) sq[pix0 + pp] = t;
            }
        }
        __syncwarp();
    }
}

// ---------------- K2: bilateral + fixup gate + normalize + reduce ----------------
// One warp per pixel (each warp handles 4 consecutive pixels sequentially).
__global__ void __launch_bounds__(256)
k_main(const float* __restrict__ fxw1, const float* __restrict__ fxb1,
       const float* __restrict__ fxg,  const float* __restrict__ fxbe,
       const float* __restrict__ fxw2, const float* __restrict__ fxb2,
       const float* __restrict__ sigp)
{
    __shared__ float w1s[N2 * 113];
    __shared__ float w2s[N2 * N2];
    __shared__ float swb[N2];
    __shared__ float cb[8][N2 + 1];
    __shared__ float fb[8][N2 + 1];
    __shared__ float sb[8][64];

    int tid = threadIdx.x;
    for (int t = tid; t < N2 * 113; t += 256) w1s[t] = fxw1[t];
    for (int t = tid; t < N2 * N2;  t += 256) w2s[t] = fxw2[t];
    if (tid < N2) {
        float sig = sigp[0];
        int dy = tid / 7 - RR, dx = tid % 7 - RR;
        swb[tid] = __expf(-(float)(dy * dy + dx * dx) / (2.f * sig * sig));
    }
    __syncthreads();

    int warp = tid >> 5, lane = tid & 31;
    int o0 = 2 * lane;
    int oa = lane, ob = lane + 32;
    bool act2 = (ob < N2);               // lane < 17

    float fb1a = fxb1[oa], fb1b = act2 ? fxb1[ob] : 0.f;
    float fga  = fxg[oa],  fgb  = act2 ? fxg[ob]  : 0.f;
    float fbea = fxbe[oa], fbeb = act2 ? fxbe[ob] : 0.f;
    float fb2a = fxb2[oa], fb2b = act2 ? fxb2[ob] : 0.f;

    for (int base = blockIdx.x * 32; base < NPIX; base += gridDim.x * 32) {
        for (int pp = 0; pp < 4; pp++) {
            int g  = base + warp * 4 + pp;
            int p  = g % HWSZ;
            int h  = p / WW, wx = p % WW;

            float2 cx  = *(const float2*)&g_px[g * 64 + o0];
            float  csq = g_pxsq[g];
            float2 sv  = *(const float2*)&g_sem[g * 64 + o0];
            sb[warp][o0]     = sv.x;
            sb[warp][o0 + 1] = sv.y;

            // ---- bilateral combined weights (pre-gate) ----
            for (int n = 0; n < N2; n++) {
                int dy = n / 7 - RR, dx = n % 7 - RR;
                int hh = h + dy, ww = wx + dx;
                float comb = 0.f;
                if ((unsigned)hh < HH && (unsigned)ww < WW) {     // warp-uniform
                    int ng = g + dy * WW + dx;
                    float2 nv = *(const float2*)&g_px[ng * 64 + o0];
                    float d = cx.x * nv.x + cx.y * nv.y;
                    #pragma unroll
                    for (int off = 16; off; off >>= 1)
                        d += __shfl_xor_sync(0xffffffffu, d, off);
                    float nsq   = g_pxsq[ng];
                    float dist2 = fmaxf(nsq + csq - 2.f * d, 0.f);
                    comb = __expf(-dist2 * (1.f / 128.f)) * swb[n];
                }
                if (lane == 0) cb[warp][n] = comb;
            }
            __syncwarp();

            // ---- fixup conv1 (49 outs from [cb(49), sem(64)]) ----
            float fa = fb1a, fbv = fb1b;
            #pragma unroll 7
            for (int j = 0; j < N2; j++) {
                float xj = cb[warp][j];
                fa += w1s[oa * 113 + j] * xj;
                if (act2) fbv += w1s[ob * 113 + j] * xj;
            }
            #pragma unroll 8
            for (int c = 0; c < 64; c++) {
                float xc = sb[warp][c];
                fa += w1s[oa * 113 + 49 + c] * xc;
                if (act2) fbv += w1s[ob * 113 + 49 + c] * xc;
            }

            // ---- LN over 49 + SiLU ----
            float s = fa + (act2 ? fbv : 0.f);
            float q = fa * fa + (act2 ? fbv * fbv : 0.f);
            #pragma unroll
            for (int off = 16; off; off >>= 1) {
                s += __shfl_xor_sync(0xffffffffu, s, off);
                q += __shfl_xor_sync(0xffffffffu, q, off);
            }
            float mean = s * (1.f / 49.f);
            float var  = q * (1.f / 49.f) - mean * mean;
            float rstd = rsqrtf(var + 1e-6f);
            float va = fga * (fa  - mean) * rstd + fbea;
            float vb = fgb * (fbv - mean) * rstd + fbeb;
            va = va / (1.f + __expf(-va));
            vb = vb / (1.f + __expf(-vb));
            fb[warp][oa] = va;
            if (act2) fb[warp][ob] = vb;
            __syncwarp();

            // ---- fixup conv2 (49x49) ----
            float ha = fb2a, hb = fb2b;
            #pragma unroll 7
            for (int j = 0; j < N2; j++) {
                float xj = fb[warp][j];
                ha += w2s[oa * N2 + j] * xj;
                if (act2) hb += w2s[ob * N2 + j] * xj;
            }

            // ---- gate + normalize ----
            float ca  = cb[warp][oa] * (1.f + 1.f / (1.f + __expf(-ha)));
            float cbl = act2 ? cb[warp][ob] * (1.f + 1.f / (1.f + __expf(-hb))) : 0.f;
            float tot = ca + cbl;
            #pragma unroll
            for (int off = 16; off; off >>= 1)
                tot += __shfl_xor_sync(0xffffffffu, tot, off);
            float inv = 1.f / (tot + 1e-7f);
            __syncwarp();
            cb[warp][oa] = ca * inv;
            if (act2) cb[warp][ob] = cbl * inv;
            __syncwarp();

            // ---- neighborhood-weighted reduction of spatial feats ----
            float2 outv = make_float2(0.f, 0.f);
            for (int n = 0; n < N2; n++) {
                int dy = n / 7 - RR, dx = n % 7 - RR;
                int hh = h + dy, ww = wx + dx;
                if ((unsigned)hh < HH && (unsigned)ww < WW) {
                    float wn = cb[warp][n];
                    int ng = g + dy * WW + dx;
                    float2 nv = *(const float2*)&g_spa[ng * 64 + o0];
                    outv.x += wn * nv.x;
                    outv.y += wn * nv.y;
                }
            }
            *(float2*)&g_mid[g * 64 + o0] = outv;
            __syncwarp();
        }
    }
}

// ---------------- launch ----------------
extern "C" void kernel_launch(void* const* d_in, const int* in_sizes, int n_in,
                              void* d_out, int out_size)
{
    const float* spa   = (const float*)d_in[0];
    const float* sem   = (const float*)d_in[1];
    const float* rp_w1 = (const float*)d_in[2];
    const float* rp_b1 = (const float*)d_in[3];
    const float* rp_g  = (const float*)d_in[4];
    const float* rp_be = (const float*)d_in[5];
    const float* rp_w2 = (const float*)d_in[6];
    const float* rp_b2 = (const float*)d_in[7];
    const float* fx_w1 = (const float*)d_in[8];
    const float* fx_b1 = (const float*)d_in[9];
    const float* fx_g  = (const float*)d_in[10];
    const float* fx_be = (const float*)d_in[11];
    const float* fx_w2 = (const float*)d_in[12];
    const float* fx_b2 = (const float*)d_in[13];
    const float* op_w1 = (const float*)d_in[14];
    const float* op_b1 = (const float*)d_in[15];
    const float* op_g  = (const float*)d_in[16];
    const float* op_be = (const float*)d_in[17];
    const float* op_w2 = (const float*)d_in[18];
    const float* op_b2 = (const float*)d_in[19];
    const float* sig   = (const float*)d_in[20];
    float* out = (float*)d_out;

    float *p_sem, *p_spa, *p_px, *p_pxsq, *p_mid, *p_o2;
    cudaGetSymbolAddress((void**)&p_sem,  g_sem);
    cudaGetSymbolAddress((void**)&p_spa,  g_spa);
    cudaGetSymbolAddress((void**)&p_px,   g_px);
    cudaGetSymbolAddress((void**)&p_pxsq, g_pxsq);
    cudaGetSymbolAddress((void**)&p_mid,  g_mid);
    cudaGetSymbolAddress((void**)&p_o2,   g_o2);

    dim3 tb(32, 8);
    dim3 tg(HWSZ / 32, BB);

    k_t_c2p<<<tg, tb>>>(spa, p_spa);
    k_t_c2p<<<tg, tb>>>(sem, p_sem);

    k_proj<true, true><<<784, 256>>>(p_sem, p_px, p_pxsq,
                                     rp_w1, rp_b1, rp_g, rp_be, rp_w2, rp_b2);

    k_main<<<784, 256>>>(fx_w1, fx_b1, fx_g, fx_be, fx_w2, fx_b2, sig);

    k_proj<false, false><<<784, 256>>>(p_mid, p_o2, nullptr,
                                       op_w1, op_b1, op_g, op_be, op_w2, op_b2);

    k_t_p2c<<<tg, tb>>>(p_o2, out);
}

// round 6
// speedup vs baseline: 1.0018x; 1.0018x over previous
#include <cuda_runtime.h>
#include <math.h>

#define HH   112
#define WW   112
#define HWSZ 12544          // 112*112
#define BB   2
#define NPIX 25088          // B*H*W
#define CC   64
#define N2   49
#define RR   3

// ---------------- scratch (pixel-major layouts) ----------------
__device__ float g_sem [NPIX * CC];   // semantic, [pix][c]
__device__ float g_spa [NPIX * CC];   // spatial,  [pix][c]
__device__ float g_px  [NPIX * CC];   // range_proj output
__device__ float g_pxsq[NPIX];        // sum_c px^2 per pixel
__device__ float g_mid [NPIX * CC];   // neighborhood-reduced feats
__device__ float g_o2  [NPIX * CC];   // output_proj result (pixel-major)

// ---------------- K0: [B,C,HW] -> [pix,C] transpose ----------------
__global__ void k_t_c2p(const float* __restrict__ src, float* __restrict__ dst) {
    __shared__ float s[64][33];
    int b  = blockIdx.y;
    int p0 = blockIdx.x * 32;
    int tx = threadIdx.x, ty = threadIdx.y;        // 32 x 8
    #pragma unroll
    for (int c = ty; c < 64; c += 8)
        s[c][tx] = src[(b * 64 + c) * HWSZ + p0 + tx];
    __syncthreads();
    #pragma unroll
    for (int i = ty; i < 32; i += 8) {
        int base = (b * HWSZ + p0 + i) * 64;
        dst[base + tx]      = s[tx][i];
        dst[base + 32 + tx] = s[tx + 32][i];
    }
}

// ---------------- K4: [pix,C] -> [B,C,HW] transpose ----------------
__global__ void k_t_p2c(const float* __restrict__ src, float* __restrict__ dst) {
    __shared__ float s[64][33];
    int b  = blockIdx.y;
    int p0 = blockIdx.x * 32;
    int tx = threadIdx.x, ty = threadIdx.y;
    #pragma unroll
    for (int i = ty; i < 32; i += 8) {
        int base = (b * HWSZ + p0 + i) * 64;
        s[tx][i]      = src[base + tx];
        s[tx + 32][i] = src[base + 32 + tx];
    }
    __syncthreads();
    #pragma unroll
    for (int c = ty; c < 64; c += 8)
        dst[(b * 64 + c) * HWSZ + p0 + tx] = s[c][tx];
}

// ---------------- K1/K3: conv1x1 -> LN -> (SiLU) -> conv1x1 ----------------
// pixel-major in/out. One warp processes 4 pixels; 8 warps/block => 32 pix/iter.
template<bool SILU, bool WSQ>
__global__ void __launch_bounds__(256)
k_proj(const float* __restrict__ in, float* __restrict__ out, float* __restrict__ sq,
       const float* __restrict__ w1, const float* __restrict__ b1,
       const float* __restrict__ gg, const float* __restrict__ bb,
       const float* __restrict__ w2, const float* __restrict__ b2)
{
    __shared__ float w1t[64 * 64];           // w1t[k*64+o] = w1[o*64+k]
    __shared__ float w2t[64 * 64];
    __shared__ float xb[8][4][64];

    int tid = threadIdx.x;
    for (int t = tid; t < 4096; t += 256) {
        int o = t >> 6, k = t & 63;
        w1t[k * 64 + o] = w1[t];
        w2t[k * 64 + o] = w2[t];
    }
    __syncthreads();

    int warp = tid >> 5, lane = tid & 31;
    int o0 = 2 * lane, o1 = o0 + 1;
    float b1a = b1[o0], b1b = b1[o1];
    float b2a = b2[o0], b2b = b2[o1];
    float ga  = gg[o0], gb  = gg[o1];
    float bea = bb[o0], beb = bb[o1];

    for (int base = blockIdx.x * 32; base < NPIX; base += gridDim.x * 32) {
        int pix0 = base + warp * 4;

        #pragma unroll
        for (int pp = 0; pp < 4; pp++) {
            float2 v = *(const float2*)&in[(pix0 + pp) * 64 + o0];
            xb[warp][pp][o0] = v.x;
            xb[warp][pp][o1] = v.y;
        }
        __syncwarp();

        float2 acc[4];
        #pragma unroll
        for (int pp = 0; pp < 4; pp++) acc[pp] = make_float2(b1a, b1b);
        #pragma unroll 8
        for (int k = 0; k < 64; k++) {
            float2 wv = *(const float2*)&w1t[k * 64 + o0];
            float x0 = xb[warp][0][k], x1 = xb[warp][1][k];
            float x2 = xb[warp][2][k], x3 = xb[warp][3][k];
            acc[0].x += wv.x * x0; acc[0].y += wv.y * x0;
            acc[1].x += wv.x * x1; acc[1].y += wv.y * x1;
            acc[2].x += wv.x * x2; acc[2].y += wv.y * x2;
            acc[3].x += wv.x * x3; acc[3].y += wv.y * x3;
        }
        __syncwarp();

        // LayerNorm (+SiLU) per pixel over 64 channels; write back into xb
        #pragma unroll
        for (int pp = 0; pp < 4; pp++) {
            float s = acc[pp].x + acc[pp].y;
            float q = acc[pp].x * acc[pp].x + acc[pp].y * acc[pp].y;
            #pragma unroll
            for (int off = 16; off; off >>= 1) {
                s += __shfl_xor_sync(0xffffffffu, s, off);
                q += __shfl_xor_sync(0xffffffffu, q, off);
            }
            float mean = s * (1.f / 64.f);
            float var  = q * (1.f / 64.f) - mean * mean;
            float rstd = rsqrtf(var + 1e-6f);
            float v0 = ga * (acc[pp].x - mean) * rstd + bea;
            float v1 = gb * (acc[pp].y - mean) * rstd + beb;
            if (SILU) {
                v0 = v0 / (1.f + __expf(-v0));
                v1 = v1 / (1.f + __expf(-v1));
            }
            xb[warp][pp][o0] = v0;
            xb[warp][pp][o1] = v1;
        }
        __syncwarp();

        #pragma unroll
        for (int pp = 0; pp < 4; pp++) acc[pp] = make_float2(b2a, b2b);
        #pragma unroll 8
        for (int k = 0; k < 64; k++) {
            float2 wv = *(const float2*)&w2t[k * 64 + o0];
            float x0 = xb[warp][0][k], x1 = xb[warp][1][k];
            float x2 = xb[warp][2][k], x3 = xb[warp][3][k];
            acc[0].x += wv.x * x0; acc[0].y += wv.y * x0;
            acc[1].x += wv.x * x1; acc[1].y += wv.y * x1;
            acc[2].x += wv.x * x2; acc[2].y += wv.y * x2;
            acc[3].x += wv.x * x3; acc[3].y += wv.y * x3;
        }

        #pragma unroll
        for (int pp = 0; pp < 4; pp++) {
            *(float2*)&out[(pix0 + pp) * 64 + o0] = acc[pp];
            if (WSQ) {
                float t = acc[pp].x * acc[pp].x + acc[pp].y * acc[pp].y;
                #pragma unroll
                for (int off = 16; off; off >>= 1)
                    t += __shfl_xor_sync(0xffffffffu, t, off);
                if (lane == 0) sq[pix0 + pp] = t;
            }
        }
        __syncwarp();
    }
}

// ---------------- K2: bilateral + fixup gate + normalize + reduce ----------------
// One warp per pixel (each warp handles 4 consecutive pixels sequentially).
__global__ void __launch_bounds__(256)
k_main(const float* __restrict__ fxw1, const float* __restrict__ fxb1,
       const float* __restrict__ fxg,  const float* __restrict__ fxbe,
       const float* __restrict__ fxw2, const float* __restrict__ fxb2,
       const float* __restrict__ sigp)
{
    __shared__ float w1s[N2 * 113];
    __shared__ float w2s[N2 * N2];
    __shared__ float swb[N2];
    __shared__ float cb[8][N2 + 1];
    __shared__ float fb[8][N2 + 1];
    __shared__ float sb[8][64];

    int tid = threadIdx.x;
    for (int t = tid; t < N2 * 113; t += 256) w1s[t] = fxw1[t];
    for (int t = tid; t < N2 * N2;  t += 256) w2s[t] = fxw2[t];
    if (tid < N2) {
        float sig = sigp[0];
        int dy = tid / 7 - RR, dx = tid % 7 - RR;
        swb[tid] = __expf(-(float)(dy * dy + dx * dx) / (2.f * sig * sig));
    }
    __syncthreads();

    int warp = tid >> 5, lane = tid & 31;
    int o0 = 2 * lane;
    int oa = lane, ob = lane + 32;
    bool act2 = (ob < N2);               // lane < 17

    float fb1a = fxb1[oa], fb1b = act2 ? fxb1[ob] : 0.f;
    float fga  = fxg[oa],  fgb  = act2 ? fxg[ob]  : 0.f;
    float fbea = fxbe[oa], fbeb = act2 ? fxbe[ob] : 0.f;
    float fb2a = fxb2[oa], fb2b = act2 ? fxb2[ob] : 0.f;

    for (int base = blockIdx.x * 32; base < NPIX; base += gridDim.x * 32) {
        for (int pp = 0; pp < 4; pp++) {
            int g  = base + warp * 4 + pp;
            int p  = g % HWSZ;
            int h  = p / WW, wx = p % WW;

            float2 cx  = *(const float2*)&g_px[g * 64 + o0];
            float  csq = g_pxsq[g];
            float2 sv  = *(const float2*)&g_sem[g * 64 + o0];
            sb[warp][o0]     = sv.x;
            sb[warp][o0 + 1] = sv.y;

            // ---- bilateral combined weights (pre-gate) ----
            for (int n = 0; n < N2; n++) {
                int dy = n / 7 - RR, dx = n % 7 - RR;
                int hh = h + dy, ww = wx + dx;
                float comb = 0.f;
                if ((unsigned)hh < HH && (unsigned)ww < WW) {     // warp-uniform
                    int ng = g + dy * WW + dx;
                    float2 nv = *(const float2*)&g_px[ng * 64 + o0];
                    float d = cx.x * nv.x + cx.y * nv.y;
                    #pragma unroll
                    for (int off = 16; off; off >>= 1)
                        d += __shfl_xor_sync(0xffffffffu, d, off);
                    float nsq   = g_pxsq[ng];
                    float dist2 = fmaxf(nsq + csq - 2.f * d, 0.f);
                    comb = __expf(-dist2 * (1.f / 128.f)) * swb[n];
                }
                if (lane == 0) cb[warp][n] = comb;
            }
            __syncwarp();

            // ---- fixup conv1 (49 outs from [cb(49), sem(64)]) ----
            float fa = fb1a, fbv = fb1b;
            #pragma unroll 7
            for (int j = 0; j < N2; j++) {
                float xj = cb[warp][j];
                fa += w1s[oa * 113 + j] * xj;
                if (act2) fbv += w1s[ob * 113 + j] * xj;
            }
            #pragma unroll 8
            for (int c = 0; c < 64; c++) {
                float xc = sb[warp][c];
                fa += w1s[oa * 113 + 49 + c] * xc;
                if (act2) fbv += w1s[ob * 113 + 49 + c] * xc;
            }

            // ---- LN over 49 + SiLU ----
            float s = fa + (act2 ? fbv : 0.f);
            float q = fa * fa + (act2 ? fbv * fbv : 0.f);
            #pragma unroll
            for (int off = 16; off; off >>= 1) {
                s += __shfl_xor_sync(0xffffffffu, s, off);
                q += __shfl_xor_sync(0xffffffffu, q, off);
            }
            float mean = s * (1.f / 49.f);
            float var  = q * (1.f / 49.f) - mean * mean;
            float rstd = rsqrtf(var + 1e-6f);
            float va = fga * (fa  - mean) * rstd + fbea;
            float vb = fgb * (fbv - mean) * rstd + fbeb;
            va = va / (1.f + __expf(-va));
            vb = vb / (1.f + __expf(-vb));
            fb[warp][oa] = va;
            if (act2) fb[warp][ob] = vb;
            __syncwarp();

            // ---- fixup conv2 (49x49) ----
            float ha = fb2a, hb = fb2b;
            #pragma unroll 7
            for (int j = 0; j < N2; j++) {
                float xj = fb[warp][j];
                ha += w2s[oa * N2 + j] * xj;
                if (act2) hb += w2s[ob * N2 + j] * xj;
            }

            // ---- gate + normalize ----
            float ca  = cb[warp][oa] * (1.f + 1.f / (1.f + __expf(-ha)));
            float cbl = act2 ? cb[warp][ob] * (1.f + 1.f / (1.f + __expf(-hb))) : 0.f;
            float tot = ca + cbl;
            #pragma unroll
            for (int off = 16; off; off >>= 1)
                tot += __shfl_xor_sync(0xffffffffu, tot, off);
            float inv = 1.f / (tot + 1e-7f);
            __syncwarp();
            cb[warp][oa] = ca * inv;
            if (act2) cb[warp][ob] = cbl * inv;
            __syncwarp();

            // ---- neighborhood-weighted reduction of spatial feats ----
            float2 outv = make_float2(0.f, 0.f);
            for (int n = 0; n < N2; n++) {
                int dy = n / 7 - RR, dx = n % 7 - RR;
                int hh = h + dy, ww = wx + dx;
                if ((unsigned)hh < HH && (unsigned)ww < WW) {
                    float wn = cb[warp][n];
                    int ng = g + dy * WW + dx;
                    float2 nv = *(const float2*)&g_spa[ng * 64 + o0];
                    outv.x += wn * nv.x;
                    outv.y += wn * nv.y;
                }
            }
            *(float2*)&g_mid[g * 64 + o0] = outv;
            __syncwarp();
        }
    }
}

// ---------------- launch ----------------
extern "C" void kernel_launch(void* const* d_in, const int* in_sizes, int n_in,
                              void* d_out, int out_size)
{
    const float* spa   = (const float*)d_in[0];
    const float* sem   = (const float*)d_in[1];
    const float* rp_w1 = (const float*)d_in[2];
    const float* rp_b1 = (const float*)d_in[3];
    const float* rp_g  = (const float*)d_in[4];
    const float* rp_be = (const float*)d_in[5];
    const float* rp_w2 = (const float*)d_in[6];
    const float* rp_b2 = (const float*)d_in[7];
    const float* fx_w1 = (const float*)d_in[8];
    const float* fx_b1 = (const float*)d_in[9];
    const float* fx_g  = (const float*)d_in[10];
    const float* fx_be = (const float*)d_in[11];
    const float* fx_w2 = (const float*)d_in[12];
    const float* fx_b2 = (const float*)d_in[13];
    const float* op_w1 = (const float*)d_in[14];
    const float* op_b1 = (const float*)d_in[15];
    const float* op_g  = (const float*)d_in[16];
    const float* op_be = (const float*)d_in[17];
    const float* op_w2 = (const float*)d_in[18];
    const float* op_b2 = (const float*)d_in[19];
    const float* sig   = (const float*)d_in[20];
    float* out = (float*)d_out;

    float *p_sem, *p_spa, *p_px, *p_pxsq, *p_mid, *p_o2;
    cudaGetSymbolAddress((void**)&p_sem,  g_sem);
    cudaGetSymbolAddress((void**)&p_spa,  g_spa);
    cudaGetSymbolAddress((void**)&p_px,   g_px);
    cudaGetSymbolAddress((void**)&p_pxsq, g_pxsq);
    cudaGetSymbolAddress((void**)&p_mid,  g_mid);
    cudaGetSymbolAddress((void**)&p_o2,   g_o2);

    dim3 tb(32, 8);
    dim3 tg(HWSZ / 32, BB);

    k_t_c2p<<<tg, tb>>>(spa, p_spa);
    k_t_c2p<<<tg, tb>>>(sem, p_sem);

    k_proj<true, true><<<784, 256>>>(p_sem, p_px, p_pxsq,
                                     rp_w1, rp_b1, rp_g, rp_be, rp_w2, rp_b2);

    k_main<<<784, 256>>>(fx_w1, fx_b1, fx_g, fx_be, fx_w2, fx_b2, sig);

    k_proj<false, false><<<784, 256>>>(p_mid, p_o2, nullptr,
                                       op_w1, op_b1, op_g, op_be, op_w2, op_b2);

    k_t_p2c<<<tg, tb>>>(p_o2, out);
}

// round 11
// speedup vs baseline: 1.0038x; 1.0021x over previous
#include <cuda_runtime.h>
#include <math.h>

#define HH   112
#define WW   112
#define HWSZ 12544          // 112*112
#define BB   2
#define NPIX 25088          // B*H*W
#define CC   64
#define N2   49
#define RR   3

// ---------------- scratch (pixel-major layouts) ----------------
__device__ float g_sem [NPIX * CC];   // semantic, [pix][c]
__device__ float g_spa [NPIX * CC];   // spatial,  [pix][c]
__device__ float g_px  [NPIX * CC];   // range_proj output
__device__ float g_pxsq[NPIX];        // sum_c px^2 per pixel
__device__ float g_mid [NPIX * CC];   // neighborhood-reduced feats
__device__ float g_o2  [NPIX * CC];   // output_proj result (pixel-major)

// ---------------- K0: [B,C,HW] -> [pix,C] transpose ----------------
__global__ void k_t_c2p(const float* __restrict__ src, float* __restrict__ dst) {
    __shared__ float s[64][33];
    int b  = blockIdx.y;
    int p0 = blockIdx.x * 32;
    int tx = threadIdx.x, ty = threadIdx.y;        // 32 x 8
    #pragma unroll
    for (int c = ty; c < 64; c += 8)
        s[c][tx] = src[(b * 64 + c) * HWSZ + p0 + tx];
    __syncthreads();
    #pragma unroll
    for (int i = ty; i < 32; i += 8) {
        int base = (b * HWSZ + p0 + i) * 64;
        dst[base + tx]      = s[tx][i];
        dst[base + 32 + tx] = s[tx + 32][i];
    }
}

// ---------------- K4: [pix,C] -> [B,C,HW] transpose ----------------
__global__ void k_t_p2c(const float* __restrict__ src, float* __restrict__ dst) {
    __shared__ float s[64][33];
    int b  = blockIdx.y;
    int p0 = blockIdx.x * 32;
    int tx = threadIdx.x, ty = threadIdx.y;
    #pragma unroll
    for (int i = ty; i < 32; i += 8) {
        int base = (b * HWSZ + p0 + i) * 64;
        s[tx][i]      = src[base + tx];
        s[tx + 32][i] = src[base + 32 + tx];
    }
    __syncthreads();
    #pragma unroll
    for (int c = ty; c < 64; c += 8)
        dst[(b * 64 + c) * HWSZ + p0 + tx] = s[c][tx];
}

// ---------------- K1/K3: conv1x1 -> LN -> (SiLU) -> conv1x1 ----------------
// pixel-major in/out. One warp processes 4 pixels; 8 warps/block => 32 pix/iter.
template<bool SILU, bool WSQ>
__global__ void __launch_bounds__(256)
k_proj(const float* __restrict__ in, float* __restrict__ out, float* __restrict__ sq,
       const float* __restrict__ w1, const float* __restrict__ b1,
       const float* __restrict__ gg, const float* __restrict__ bb,
       const float* __restrict__ w2, const float* __restrict__ b2)
{
    __shared__ float w1t[64 * 64];           // w1t[k*64+o] = w1[o*64+k]
    __shared__ float w2t[64 * 64];
    __shared__ float xb[8][4][64];

    int tid = threadIdx.x;
    for (int t = tid; t < 4096; t += 256) {
        int o = t >> 6, k = t & 63;
        w1t[k * 64 + o] = w1[t];
        w2t[k * 64 + o] = w2[t];
    }
    __syncthreads();

    int warp = tid >> 5, lane = tid & 31;
    int o0 = 2 * lane, o1 = o0 + 1;
    float b1a = b1[o0], b1b = b1[o1];
    float b2a = b2[o0], b2b = b2[o1];
    float ga  = gg[o0], gb  = gg[o1];
    float bea = bb[o0], beb = bb[o1];

    for (int base = blockIdx.x * 32; base < NPIX; base += gridDim.x * 32) {
        int pix0 = base + warp * 4;

        #pragma unroll
        for (int pp = 0; pp < 4; pp++) {
            float2 v = *(const float2*)&in[(pix0 + pp) * 64 + o0];
            xb[warp][pp][o0] = v.x;
            xb[warp][pp][o1] = v.y;
        }
        __syncwarp();

        float2 acc[4];
        #pragma unroll
        for (int pp = 0; pp < 4; pp++) acc[pp] = make_float2(b1a, b1b);
        #pragma unroll 8
        for (int k = 0; k < 64; k++) {
            float2 wv = *(const float2*)&w1t[k * 64 + o0];
            float x0 = xb[warp][0][k], x1 = xb[warp][1][k];
            float x2 = xb[warp][2][k], x3 = xb[warp][3][k];
            acc[0].x += wv.x * x0; acc[0].y += wv.y * x0;
            acc[1].x += wv.x * x1; acc[1].y += wv.y * x1;
            acc[2].x += wv.x * x2; acc[2].y += wv.y * x2;
            acc[3].x += wv.x * x3; acc[3].y += wv.y * x3;
        }
        __syncwarp();

        // LayerNorm (+SiLU) per pixel over 64 channels; write back into xb
        #pragma unroll
        for (int pp = 0; pp < 4; pp++) {
            float s = acc[pp].x + acc[pp].y;
            float q = acc[pp].x * acc[pp].x + acc[pp].y * acc[pp].y;
            #pragma unroll
            for (int off = 16; off; off >>= 1) {
                s += __shfl_xor_sync(0xffffffffu, s, off);
                q += __shfl_xor_sync(0xffffffffu, q, off);
            }
            float mean = s * (1.f / 64.f);
            float var  = q * (1.f / 64.f) - mean * mean;
            float rstd = rsqrtf(var + 1e-6f);
            float v0 = ga * (acc[pp].x - mean) * rstd + bea;
            float v1 = gb * (acc[pp].y - mean) * rstd + beb;
            if (SILU) {
                v0 = v0 / (1.f + __expf(-v0));
                v1 = v1 / (1.f + __expf(-v1));
            }
            xb[warp][pp][o0] = v0;
            xb[warp][pp][o1] = v1;
        }
        __syncwarp();

        #pragma unroll
        for (int pp = 0; pp < 4; pp++) acc[pp] = make_float2(b2a, b2b);
        #pragma unroll 8
        for (int k = 0; k < 64; k++) {
            float2 wv = *(const float2*)&w2t[k * 64 + o0];
            float x0 = xb[warp][0][k], x1 = xb[warp][1][k];
            float x2 = xb[warp][2][k], x3 = xb[warp][3][k];
            acc[0].x += wv.x * x0; acc[0].y += wv.y * x0;
            acc[1].x += wv.x * x1; acc[1].y += wv.y * x1;
            acc[2].x += wv.x * x2; acc[2].y += wv.y * x2;
            acc[3].x += wv.x * x3; acc[3].y += wv.y * x3;
        }

        #pragma unroll
        for (int pp = 0; pp < 4; pp++) {
            *(float2*)&out[(pix0 + pp) * 64 + o0] = acc[pp];
            if (WSQ) {
                float t = acc[pp].x * acc[pp].x + acc[pp].y * acc[pp].y;
                #pragma unroll
                for (int off = 16; off; off >>= 1)
                    t += __shfl_xor_sync(0xffffffffu, t, off);
                if (lane == 0) sq[pix0 + pp] = t;
            }
        }
        __syncwarp();
    }
}

// ---------------- K2: bilateral + fixup gate + normalize + reduce ----------------
// One warp per pixel (each warp handles 4 consecutive pixels sequentially).
__global__ void __launch_bounds__(256)
k_main(const float* __restrict__ fxw1, const float* __restrict__ fxb1,
       const float* __restrict__ fxg,  const float* __restrict__ fxbe,
       const float* __restrict__ fxw2, const float* __restrict__ fxb2,
       const float* __restrict__ sigp)
{
    __shared__ float w1s[N2 * 113];
    __shared__ float w2s[N2 * N2];
    __shared__ float swb[N2];
    __shared__ float cb[8][N2 + 1];
    __shared__ float fb[8][N2 + 1];
    __shared__ float sb[8][64];

    int tid = threadIdx.x;
    for (int t = tid; t < N2 * 113; t += 256) w1s[t] = fxw1[t];
    for (int t = tid; t < N2 * N2;  t += 256) w2s[t] = fxw2[t];
    if (tid < N2) {
        float sig = sigp[0];
        int dy = tid / 7 - RR, dx = tid % 7 - RR;
        swb[tid] = __expf(-(float)(dy * dy + dx * dx) / (2.f * sig * sig));
    }
    __syncthreads();

    int warp = tid >> 5, lane = tid & 31;
    int o0 = 2 * lane;
    int oa = lane, ob = lane + 32;
    bool act2 = (ob < N2);               // lane < 17

    float fb1a = fxb1[oa], fb1b = act2 ? fxb1[ob] : 0.f;
    float fga  = fxg[oa],  fgb  = act2 ? fxg[ob]  : 0.f;
    float fbea = fxbe[oa], fbeb = act2 ? fxbe[ob] : 0.f;
    float fb2a = fxb2[oa], fb2b = act2 ? fxb2[ob] : 0.f;

    for (int base = blockIdx.x * 32; base < NPIX; base += gridDim.x * 32) {
        for (int pp = 0; pp < 4; pp++) {
            int g  = base + warp * 4 + pp;
            int p  = g % HWSZ;
            int h  = p / WW, wx = p % WW;

            float2 cx  = *(const float2*)&g_px[g * 64 + o0];
            float  csq = g_pxsq[g];
            float2 sv  = *(const float2*)&g_sem[g * 64 + o0];
            sb[warp][o0]     = sv.x;
            sb[warp][o0 + 1] = sv.y;

            // ---- bilateral combined weights (pre-gate) ----
            for (int n = 0; n < N2; n++) {
                int dy = n / 7 - RR, dx = n % 7 - RR;
                int hh = h + dy, ww = wx + dx;
                float comb = 0.f;
                if ((unsigned)hh < HH && (unsigned)ww < WW) {     // warp-uniform
                    int ng = g + dy * WW + dx;
                    float2 nv = *(const float2*)&g_px[ng * 64 + o0];
                    float d = cx.x * nv.x + cx.y * nv.y;
                    #pragma unroll
                    for (int off = 16; off; off >>= 1)
                        d += __shfl_xor_sync(0xffffffffu, d, off);
                    float nsq   = g_pxsq[ng];
                    float dist2 = fmaxf(nsq + csq - 2.f * d, 0.f);
                    comb = __expf(-dist2 * (1.f / 128.f)) * swb[n];
                }
                if (lane == 0) cb[warp][n] = comb;
            }
            __syncwarp();

            // ---- fixup conv1 (49 outs from [cb(49), sem(64)]) ----
            float fa = fb1a, fbv = fb1b;
            #pragma unroll 7
            for (int j = 0; j < N2; j++) {
                float xj = cb[warp][j];
                fa += w1s[oa * 113 + j] * xj;
                if (act2) fbv += w1s[ob * 113 + j] * xj;
            }
            #pragma unroll 8
            for (int c = 0; c < 64; c++) {
                float xc = sb[warp][c];
                fa += w1s[oa * 113 + 49 + c] * xc;
                if (act2) fbv += w1s[ob * 113 + 49 + c] * xc;
            }

            // ---- LN over 49 + SiLU ----
            float s = fa + (act2 ? fbv : 0.f);
            float q = fa * fa + (act2 ? fbv * fbv : 0.f);
            #pragma unroll
            for (int off = 16; off; off >>= 1) {
                s += __shfl_xor_sync(0xffffffffu, s, off);
                q += __shfl_xor_sync(0xffffffffu, q, off);
            }
            float mean = s * (1.f / 49.f);
            float var  = q * (1.f / 49.f) - mean * mean;
            float rstd = rsqrtf(var + 1e-6f);
            float va = fga * (fa  - mean) * rstd + fbea;
            float vb = fgb * (fbv - mean) * rstd + fbeb;
            va = va / (1.f + __expf(-va));
            vb = vb / (1.f + __expf(-vb));
            fb[warp][oa] = va;
            if (act2) fb[warp][ob] = vb;
            __syncwarp();

            // ---- fixup conv2 (49x49) ----
            float ha = fb2a, hb = fb2b;
            #pragma unroll 7
            for (int j = 0; j < N2; j++) {
                float xj = fb[warp][j];
                ha += w2s[oa * N2 + j] * xj;
                if (act2) hb += w2s[ob * N2 + j] * xj;
            }

            // ---- gate + normalize ----
            float ca  = cb[warp][oa] * (1.f + 1.f / (1.f + __expf(-ha)));
            float cbl = act2 ? cb[warp][ob] * (1.f + 1.f / (1.f + __expf(-hb))) : 0.f;
            float tot = ca + cbl;
            #pragma unroll
            for (int off = 16; off; off >>= 1)
                tot += __shfl_xor_sync(0xffffffffu, tot, off);
            float inv = 1.f / (tot + 1e-7f);
            __syncwarp();
            cb[warp][oa] = ca * inv;
            if (act2) cb[warp][ob] = cbl * inv;
            __syncwarp();

            // ---- neighborhood-weighted reduction of spatial feats ----
            float2 outv = make_float2(0.f, 0.f);
            for (int n = 0; n < N2; n++) {
                int dy = n / 7 - RR, dx = n % 7 - RR;
                int hh = h + dy, ww = wx + dx;
                if ((unsigned)hh < HH && (unsigned)ww < WW) {
                    float wn = cb[warp][n];
                    int ng = g + dy * WW + dx;
                    float2 nv = *(const float2*)&g_spa[ng * 64 + o0];
                    outv.x += wn * nv.x;
                    outv.y += wn * nv.y;
                }
            }
            *(float2*)&g_mid[g * 64 + o0] = outv;
            __syncwarp();
        }
    }
}

// ---------------- launch ----------------
extern "C" void kernel_launch(void* const* d_in, const int* in_sizes, int n_in,
                              void* d_out, int out_size)
{
    const float* spa   = (const float*)d_in[0];
    const float* sem   = (const float*)d_in[1];
    const float* rp_w1 = (const float*)d_in[2];
    const float* rp_b1 = (const float*)d_in[3];
    const float* rp_g  = (const float*)d_in[4];
    const float* rp_be = (const float*)d_in[5];
    const float* rp_w2 = (const float*)d_in[6];
    const float* rp_b2 = (const float*)d_in[7];
    const float* fx_w1 = (const float*)d_in[8];
    const float* fx_b1 = (const float*)d_in[9];
    const float* fx_g  = (const float*)d_in[10];
    const float* fx_be = (const float*)d_in[11];
    const float* fx_w2 = (const float*)d_in[12];
    const float* fx_b2 = (const float*)d_in[13];
    const float* op_w1 = (const float*)d_in[14];
    const float* op_b1 = (const float*)d_in[15];
    const float* op_g  = (const float*)d_in[16];
    const float* op_be = (const float*)d_in[17];
    const float* op_w2 = (const float*)d_in[18];
    const float* op_b2 = (const float*)d_in[19];
    const float* sig   = (const float*)d_in[20];
    float* out = (float*)d_out;

    float *p_sem, *p_spa, *p_px, *p_pxsq, *p_mid, *p_o2;
    cudaGetSymbolAddress((void**)&p_sem,  g_sem);
    cudaGetSymbolAddress((void**)&p_spa,  g_spa);
    cudaGetSymbolAddress((void**)&p_px,   g_px);
    cudaGetSymbolAddress((void**)&p_pxsq, g_pxsq);
    cudaGetSymbolAddress((void**)&p_mid,  g_mid);
    cudaGetSymbolAddress((void**)&p_o2,   g_o2);

    dim3 tb(32, 8);
    dim3 tg(HWSZ / 32, BB);

    k_t_c2p<<<tg, tb>>>(spa, p_spa);
    k_t_c2p<<<tg, tb>>>(sem, p_sem);

    k_proj<true, true><<<784, 256>>>(p_sem, p_px, p_pxsq,
                                     rp_w1, rp_b1, rp_g, rp_be, rp_w2, rp_b2);

    k_main<<<784, 256>>>(fx_w1, fx_b1, fx_g, fx_be, fx_w2, fx_b2, sig);

    k_proj<false, false><<<784, 256>>>(p_mid, p_o2, nullptr,
                                       op_w1, op_b1, op_g, op_be, op_w2, op_b2);

    k_t_p2c<<<tg, tb>>>(p_o2, out);
}